// round 14
// baseline (speedup 1.0000x reference)
#include <cuda_runtime.h>
#include <cuda_bf16.h>
#include <math.h>

#define MAX_NODES 50000
#define D 16
#define NTYPES 16
#define RPB 2                         // rows per k_node block (grid.z = D/RPB)
#define TPT ((MAX_NODES + 255) / 256) // tiles per type = 196

// Scratch (allocation-free rule: __device__ globals)
__device__ int   g_cnt_out[MAX_NODES * NTYPES]; // out-edge type counts
__device__ int   g_cnt_in [MAX_NODES * NTYPES]; // in-edge type counts
__device__ int   g_pos[NTYPES];                 // bucket fill counters -> final counts
// Tile-SoA node records: [type][tile][j4 0..7][node 0..255][4]
//   j4 0..3 = normalized x, j4 4..7 = float net counts (out - in)
// Never-written slots stay 0 (static zero-init) -> zero contribution.
__device__ float g_rec[(size_t)NTYPES * TPT * 8 * 1024];

// ---------------------------------------------------------------- K0: zero counters + out
__global__ void k_zero(float* out) {
    int i = blockIdx.x * blockDim.x + threadIdx.x;
    int total4 = (MAX_NODES * NTYPES) / 4;
    if (i < total4) {
        reinterpret_cast<int4*>(g_cnt_out)[i] = make_int4(0, 0, 0, 0);
        reinterpret_cast<int4*>(g_cnt_in )[i] = make_int4(0, 0, 0, 0);
    }
    if (i < NTYPES) g_pos[i] = 0;
    if (i == 0) out[0] = 0.0f;
}

// ---------------------------------------------------------------- K1: per-edge type counts (2 atomics/edge)
__global__ void __launch_bounds__(256)
k_count(const int* __restrict__ src, const int* __restrict__ dst,
        const int* __restrict__ types, int n_edges) {
    int e = blockIdx.x * blockDim.x + threadIdx.x;
    if (e >= n_edges) return;
    int s  = src[e];
    int d  = dst[e];
    int ts = __ldg(types + s);
    int td = __ldg(types + d);
    atomicAdd(&g_cnt_out[s * NTYPES + td], 1);
    atomicAdd(&g_cnt_in [d * NTYPES + ts], 1);
}

// ---------------------------------------------------------------- K2: build tile-SoA type-sorted records
__global__ void __launch_bounds__(256)
k_prep(const float* __restrict__ reps, const int* __restrict__ types, int n_nodes) {
    __shared__ int s_hist[NTYPES], s_base[NTYPES];

    int tid  = threadIdx.x;
    int base = blockIdx.x * 256;
    int v    = base + tid;

    if (tid < NTYPES) s_hist[tid] = 0;
    __syncthreads();

    int t = 0, lrank = 0;
    float4 cf0, cf1, cf2, cf3;
    float inv = 0.0f;
    if (v < n_nodes) {
        t = __ldg(types + v);
        lrank = atomicAdd(&s_hist[t], 1);     // smem atomic
        const int4* co = reinterpret_cast<const int4*>(g_cnt_out + v * NTYPES);
        const int4* ci = reinterpret_cast<const int4*>(g_cnt_in  + v * NTYPES);
        int4 o0 = co[0], o1 = co[1], o2 = co[2], o3 = co[3];
        int4 i0 = ci[0], i1 = ci[1], i2 = ci[2], i3 = ci[3];
        int deg = i0.x+i0.y+i0.z+i0.w + i1.x+i1.y+i1.z+i1.w
                + i2.x+i2.y+i2.z+i2.w + i3.x+i3.y+i3.z+i3.w;
        inv = (deg > 0) ? rsqrtf((float)deg) : 0.0f;
        cf0 = make_float4((float)(o0.x-i0.x), (float)(o0.y-i0.y), (float)(o0.z-i0.z), (float)(o0.w-i0.w));
        cf1 = make_float4((float)(o1.x-i1.x), (float)(o1.y-i1.y), (float)(o1.z-i1.z), (float)(o1.w-i1.w));
        cf2 = make_float4((float)(o2.x-i2.x), (float)(o2.y-i2.y), (float)(o2.z-i2.z), (float)(o2.w-i2.w));
        cf3 = make_float4((float)(o3.x-i3.x), (float)(o3.y-i3.y), (float)(o3.z-i3.z), (float)(o3.w-i3.w));
    }
    __syncthreads();
    if (tid < NTYPES) s_base[tid] = atomicAdd(&g_pos[tid], s_hist[tid]);
    __syncthreads();

    if (v < n_nodes) {
        float x[D];
        #pragma unroll
        for (int i = 0; i < D; i++)
            x[i] = __ldg(reps + i * n_nodes + v) * inv;   // coalesced across warp

        int slot = s_base[t] + lrank;
        int tile = slot >> 8, off = slot & 255;
        float* tb = g_rec + ((size_t)(t * TPT + tile) * 8) * 1024;
        *reinterpret_cast<float4*>(tb + 0*1024 + off*4) = make_float4(x[0],  x[1],  x[2],  x[3]);
        *reinterpret_cast<float4*>(tb + 1*1024 + off*4) = make_float4(x[4],  x[5],  x[6],  x[7]);
        *reinterpret_cast<float4*>(tb + 2*1024 + off*4) = make_float4(x[8],  x[9],  x[10], x[11]);
        *reinterpret_cast<float4*>(tb + 3*1024 + off*4) = make_float4(x[12], x[13], x[14], x[15]);
        *reinterpret_cast<float4*>(tb + 4*1024 + off*4) = cf0;
        *reinterpret_cast<float4*>(tb + 5*1024 + off*4) = cf1;
        *reinterpret_cast<float4*>(tb + 6*1024 + off*4) = cf2;
        *reinterpret_cast<float4*>(tb + 7*1024 + off*4) = cf3;
    }
}

// ---------------------------------------------------------------- K3: weighted matvec + sum of squares
// Block = ONE (type, tile-PAIR, 2-row slice); thread handles 2 nodes.
// Record loads coalesced (tile-SoA); R rows warp-uniform smem broadcasts,
// each LDS.128 feeds 8 FMA (2 nodes); cf in TRANSPOSED smem [t][node]
// (conflict-free; previous CFPAD=20 layout had gcd(20,32)=4 -> 4-way conflicts).
__global__ void __launch_bounds__(256, 3)
k_node(const float* __restrict__ R, float* out) {
    int type  = blockIdx.y;
    int count = __ldg(&g_pos[type]);
    int base  = blockIdx.x * 512;
    if (base >= count) return;
    int ro = blockIdx.z * RPB;

    __shared__ float sR[NTYPES * RPB * 16];      // 2 KB: rows ro, ro+1 of each R[type][t]
    __shared__ float s_cf[NTYPES][512];          // 32 KB, transposed: [t][node]
    int tid = threadIdx.x;

    if (tid < 128) {                              // 128 float4 entries
        int t = tid >> 3, r = (tid >> 2) & 1, j4 = tid & 3;
        const float4* src = reinterpret_cast<const float4*>(R)
                          + (type << 10) + (t << 6) + ((ro + r) << 2) + j4;
        reinterpret_cast<float4*>(sR)[tid] = *src;
    }

    const float* ta = g_rec + (size_t)(type * TPT + blockIdx.x * 2) * 8192;
    const float* tb = ta + 8192;                  // second tile of the pair

    // coalesced LDG.128 of x (lanes read consecutive 16B)
    float4 xa0 = *reinterpret_cast<const float4*>(ta + 0*1024 + tid*4);
    float4 xa1 = *reinterpret_cast<const float4*>(ta + 1*1024 + tid*4);
    float4 xa2 = *reinterpret_cast<const float4*>(ta + 2*1024 + tid*4);
    float4 xa3 = *reinterpret_cast<const float4*>(ta + 3*1024 + tid*4);
    float4 xb0 = *reinterpret_cast<const float4*>(tb + 0*1024 + tid*4);
    float4 xb1 = *reinterpret_cast<const float4*>(tb + 1*1024 + tid*4);
    float4 xb2 = *reinterpret_cast<const float4*>(tb + 2*1024 + tid*4);
    float4 xb3 = *reinterpret_cast<const float4*>(tb + 3*1024 + tid*4);

    // stage cf transposed (conflict-free STS: lanes consecutive)
    #pragma unroll
    for (int j4 = 0; j4 < 4; j4++) {
        float4 ca = *reinterpret_cast<const float4*>(ta + (4+j4)*1024 + tid*4);
        s_cf[j4*4+0][tid] = ca.x; s_cf[j4*4+1][tid] = ca.y;
        s_cf[j4*4+2][tid] = ca.z; s_cf[j4*4+3][tid] = ca.w;
        float4 cb = *reinterpret_cast<const float4*>(tb + (4+j4)*1024 + tid*4);
        s_cf[j4*4+0][256+tid] = cb.x; s_cf[j4*4+1][256+tid] = cb.y;
        s_cf[j4*4+2][256+tid] = cb.z; s_cf[j4*4+3][256+tid] = cb.w;
    }
    __syncthreads();

    float ya0 = 0.0f, ya1 = 0.0f, yb0 = 0.0f, yb1 = 0.0f;
    #pragma unroll 1
    for (int t = 0; t < NTYPES; t++) {           // outer NOT unrolled (I$)
        float ca = s_cf[t][tid];
        float cb = s_cf[t][256 + tid];
        const float4* rb = reinterpret_cast<const float4*>(sR + t * (RPB*16));
        // row ro
        float4 r0 = rb[0], r1 = rb[1], r2 = rb[2], r3 = rb[3];
        float da = r0.x*xa0.x + r0.y*xa0.y + r0.z*xa0.z + r0.w*xa0.w
                 + r1.x*xa1.x + r1.y*xa1.y + r1.z*xa1.z + r1.w*xa1.w
                 + r2.x*xa2.x + r2.y*xa2.y + r2.z*xa2.z + r2.w*xa2.w
                 + r3.x*xa3.x + r3.y*xa3.y + r3.z*xa3.z + r3.w*xa3.w;
        float db = r0.x*xb0.x + r0.y*xb0.y + r0.z*xb0.z + r0.w*xb0.w
                 + r1.x*xb1.x + r1.y*xb1.y + r1.z*xb1.z + r1.w*xb1.w
                 + r2.x*xb2.x + r2.y*xb2.y + r2.z*xb2.z + r2.w*xb2.w
                 + r3.x*xb3.x + r3.y*xb3.y + r3.z*xb3.z + r3.w*xb3.w;
        ya0 = fmaf(ca, da, ya0);
        yb0 = fmaf(cb, db, yb0);
        // row ro+1
        float4 s0 = rb[4], s1 = rb[5], s2 = rb[6], s3 = rb[7];
        float ea = s0.x*xa0.x + s0.y*xa0.y + s0.z*xa0.z + s0.w*xa0.w
                 + s1.x*xa1.x + s1.y*xa1.y + s1.z*xa1.z + s1.w*xa1.w
                 + s2.x*xa2.x + s2.y*xa2.y + s2.z*xa2.z + s2.w*xa2.w
                 + s3.x*xa3.x + s3.y*xa3.y + s3.z*xa3.z + s3.w*xa3.w;
        float eb = s0.x*xb0.x + s0.y*xb0.y + s0.z*xb0.z + s0.w*xb0.w
                 + s1.x*xb1.x + s1.y*xb1.y + s1.z*xb1.z + s1.w*xb1.w
                 + s2.x*xb2.x + s2.y*xb2.y + s2.z*xb2.z + s2.w*xb2.w
                 + s3.x*xb3.x + s3.y*xb3.y + s3.z*xb3.z + s3.w*xb3.w;
        ya1 = fmaf(ca, ea, ya1);
        yb1 = fmaf(cb, eb, yb1);
    }

    bool va = (base + tid)       < count;
    bool vb = (base + 256 + tid) < count;
    float acc = (va ? ya0*ya0 + ya1*ya1 : 0.0f)
              + (vb ? yb0*yb0 + yb1*yb1 : 0.0f);

    // block reduce -> one atomicAdd per block
    #pragma unroll
    for (int off = 16; off > 0; off >>= 1)
        acc += __shfl_down_sync(0xFFFFFFFFu, acc, off);
    __shared__ float warp_sums[8];
    int lane = tid & 31;
    int wid  = tid >> 5;
    if (lane == 0) warp_sums[wid] = acc;
    __syncthreads();
    if (wid == 0) {
        float s = (lane < 8) ? warp_sums[lane] : 0.0f;
        #pragma unroll
        for (int off = 4; off > 0; off >>= 1)
            s += __shfl_down_sync(0xFFu, s, off);
        if (lane == 0) atomicAdd(out, s);
    }
}

// ---------------------------------------------------------------- launch
extern "C" void kernel_launch(void* const* d_in, const int* in_sizes, int n_in,
                              void* d_out, int out_size) {
    const float* reps  = (const float*)d_in[0];  // [16, n_nodes]
    const float* rmaps = (const float*)d_in[1];  // [16,16,16,16]
    const int*   eidx  = (const int*)d_in[2];    // [2, n_edges]
    const int*   types = (const int*)d_in[3];    // [n_nodes]
    float* out = (float*)d_out;

    int n_nodes = in_sizes[3];
    if (n_nodes > MAX_NODES) n_nodes = MAX_NODES;
    int n_edges = in_sizes[2] / 2;
    const int* src = eidx;
    const int* dst = eidx + n_edges;

    const int T = 256;

    k_zero <<<(MAX_NODES * NTYPES / 4 + T - 1) / T, T>>>(out);
    k_count<<<(n_edges + T - 1) / T, T>>>(src, dst, types, n_edges);
    k_prep <<<(n_nodes + T - 1) / T, T>>>(reps, types, n_nodes);

    dim3 grid((TPT + 1) / 2, NTYPES, D / RPB);   // non-working blocks exit early
    k_node <<<grid, 256>>>(rmaps, out);
}